// round 7
// baseline (speedup 1.0000x reference)
#include <cuda_runtime.h>
#include <math.h>

// x:(B,256) f32, W1:(4,256), b1:(4), weights:(L,4,3), W2:(64,4), b2:(64) -> out:(B,64)
#define MAX_L   8
#define DIN     256
#define DOUT    64
#define NQ      4
#define ROWS    256
#define THREADS 256

__device__ __forceinline__ float2 cmul(float2 a, float2 b) {
    return make_float2(fmaf(a.x, b.x, -a.y * b.y), fmaf(a.x, b.y, a.y * b.x));
}
__device__ __forceinline__ float2 cfma(float2 u, float2 a, float2 acc) {
    acc.x = fmaf(u.x, a.x, fmaf(-u.y, a.y, acc.x));
    acc.y = fmaf(u.x, a.y, fmaf( u.y, a.x, acc.y));
    return acc;
}
// tanh via MUFU exp: tanh(x) = 1 - 2/(exp(2x)+1). |err| ~ 1e-7 rel.
__device__ __forceinline__ float fast_tanh(float v) {
    float e = __expf(2.f * v);
    return 1.f - 2.f * __frcp_rn(e + 1.f);
}

// ---------------------------------------------------------------------------
// Single fused kernel, 3 blocks/SM. Block = 256 threads = 256 rows.
// Phase 1 (warp-coop GEMV): W1 in SMEM (LDS.128 per sub-iter keeps regs low);
//   warp owns 32 rows; 8 sub-iters x 4 rows; value-halving butterfly.
// Phase 2: every lane runs the 4-qubit circuit for its own row.
// Phase 3: z staged in smem, fully coalesced float4 projection stores.
// ---------------------------------------------------------------------------
__global__ void __launch_bounds__(THREADS, 3)
qproj_fused(const float* __restrict__ x,  const float* __restrict__ W1,
            const float* __restrict__ b1, const float* __restrict__ weights,
            const float* __restrict__ W2, const float* __restrict__ b2,
            float* __restrict__ out, int B, int L)
{
    __shared__ float4 w1s4[NQ * DIN / 4];   // w1s4[q*64 + j] = W1[q][4j..4j+4)
    __shared__ float  w2t[NQ][DOUT];
    __shared__ float4 b2s4[DOUT / 4];
    __shared__ float4 rots4[MAX_L * NQ * 2];
    __shared__ float4 zs[ROWS];

    const int  tid     = threadIdx.x;
    const int  lane    = tid & 31;
    const int  wid     = tid >> 5;
    const long rowBase = (long)blockIdx.x * ROWS;
    const bool fullBlk = (rowBase + ROWS) <= (long)B;

    // ---- stage W1 + small weights + compute Rot matrices in-block ----
    if (tid < NQ * DIN / 4)
        w1s4[tid] = reinterpret_cast<const float4*>(W1)[tid];
    if (tid < DOUT) {
        #pragma unroll
        for (int i = 0; i < NQ; ++i) w2t[i][tid] = W2[tid * NQ + i];
    }
    if (tid < DOUT / 4) b2s4[tid] = reinterpret_cast<const float4*>(b2)[tid];
    if (tid >= 64 && tid < 64 + L * NQ) {
        int idx = tid - 64;                 // l*4 + wire
        float phi = weights[idx * 3 + 0];
        float th  = weights[idx * 3 + 1];
        float om  = weights[idx * 3 + 2];
        float s, c;   sincosf(0.5f * th, &s, &c);
        float sa, ca; sincosf(0.5f * (phi - om), &sa, &ca);   // (phi-omega)/2
        float sb, cb; sincosf(0.5f * (phi + om), &sb, &cb);   // (phi+omega)/2
        rots4[idx * 2 + 0] = make_float4( cb * c, -sb * c,    // U00
                                         -ca * s, -sa * s);   // U01
        rots4[idx * 2 + 1] = make_float4( ca * s, -sa * s,    // U10
                                          cb * c,  sb * c);   // U11
    }
    __syncthreads();

    // ---- phase 1: f = tanh(x @ W1^T + b1) * pi (warp-cooperative) ----
    const float4 b1v = *reinterpret_cast<const float4*>(b1);

    const long warpRow = rowBase + wid * 32;
    const bool hiR1 = (lane & 16) != 0;     // keep rows {2,3} at off=16
    const bool hiR0 = (lane & 8)  != 0;     // keep odd row of pair at off=8
    const int  redisSrc = 8 * (lane & 3);   // source lane for my row's sums

    float m0 = 0.f, m1 = 0.f, m2 = 0.f, m3 = 0.f;   // my row's 4 dot products

    #pragma unroll
    for (int s = 0; s < 8; ++s) {
        float4 xa[4], xb[4];
        if (fullBlk) {
            #pragma unroll
            for (int r = 0; r < 4; ++r) {            // 8 LDG.128 in flight
                const float* xp = x + (warpRow + s * 4 + r) * DIN + 4 * lane;
                xa[r] = *reinterpret_cast<const float4*>(xp);
                xb[r] = *reinterpret_cast<const float4*>(xp + 128);
            }
        } else {
            #pragma unroll
            for (int r = 0; r < 4; ++r) {
                long rr = warpRow + s * 4 + r;
                if (rr >= B) rr = (long)B - 1;
                const float* xp = x + rr * DIN + 4 * lane;
                xa[r] = *reinterpret_cast<const float4*>(xp);
                xb[r] = *reinterpret_cast<const float4*>(xp + 128);
            }
        }
        float acc[4][NQ];
        #pragma unroll
        for (int q = 0; q < NQ; ++q) {
            // weights from SMEM (conflict-free LDS.128); under the reg cap
            // ptxas keeps these in-loop instead of hoisting 32 regs.
            const float4 wa = w1s4[q * 64 + lane];
            const float4 wb = w1s4[q * 64 + 32 + lane];
            #pragma unroll
            for (int r = 0; r < 4; ++r) {
                float a;
                a = xa[r].x * wa.x;
                a = fmaf(xa[r].y, wa.y, a);
                a = fmaf(xa[r].z, wa.z, a);
                a = fmaf(xa[r].w, wa.w, a);
                a = fmaf(xb[r].x, wb.x, a);
                a = fmaf(xb[r].y, wb.y, a);
                a = fmaf(xb[r].z, wb.z, a);
                a = fmaf(xb[r].w, wb.w, a);
                acc[r][q] = a;
            }
        }

        // ---- value-halving butterfly ----
        float t8[2][NQ];
        #pragma unroll
        for (int rl = 0; rl < 2; ++rl)
            #pragma unroll
            for (int q = 0; q < NQ; ++q) {
                float kp = hiR1 ? acc[rl + 2][q] : acc[rl][q];
                float gv = hiR1 ? acc[rl][q]     : acc[rl + 2][q];
                t8[rl][q] = kp + __shfl_xor_sync(0xffffffffu, gv, 16);
            }
        float t4[NQ];
        #pragma unroll
        for (int q = 0; q < NQ; ++q) {
            float kp = hiR0 ? t8[1][q] : t8[0][q];
            float gv = hiR0 ? t8[0][q] : t8[1][q];
            t4[q] = kp + __shfl_xor_sync(0xffffffffu, gv, 8);
        }
        #pragma unroll
        for (int off = 4; off >= 1; off >>= 1)
            #pragma unroll
            for (int q = 0; q < NQ; ++q)
                t4[q] += __shfl_xor_sync(0xffffffffu, t4[q], off);

        float r0 = __shfl_sync(0xffffffffu, t4[0], redisSrc);
        float r1 = __shfl_sync(0xffffffffu, t4[1], redisSrc);
        float r2 = __shfl_sync(0xffffffffu, t4[2], redisSrc);
        float r3 = __shfl_sync(0xffffffffu, t4[3], redisSrc);
        if ((lane >> 2) == s) { m0 = r0; m1 = r1; m2 = r2; m3 = r3; }
    }

    const float PI_F = 3.14159265358979323846f;
    float fv[NQ];
    fv[0] = fast_tanh(m0 + b1v.x) * PI_F;
    fv[1] = fast_tanh(m1 + b1v.y) * PI_F;
    fv[2] = fast_tanh(m2 + b1v.z) * PI_F;
    fv[3] = fast_tanh(m3 + b1v.w) * PI_F;

    // ---- phase 2: circuit (per-lane row; atan eliminated via identities) ----
    float2 ga[NQ], gb[NQ];
    #pragma unroll
    for (int i = 0; i < NQ; ++i) {
        float t  = fv[i];
        float t2 = t * t;
        float st = t * rsqrtf(1.f + t2);
        float u  = sqrtf(fmaxf(0.5f * (1.f - st), 0.f));
        float v  = sqrtf(fmaxf(0.5f * (1.f + st), 0.f));
        float t4 = t2 * t2;
        float r2 = rsqrtf(1.f + t4);
        float cp = sqrtf(fmaxf(0.5f * (1.f + r2), 0.f));
        float sp = sqrtf(fmaxf(0.5f * (1.f - r2), 0.f));
        ga[i] = make_float2(u * cp, -u * sp);
        gb[i] = make_float2(v * cp,  v * sp);
    }

    float2 amp[16];
    {
        float2 p01[4], p23[4];
        #pragma unroll
        for (int i0 = 0; i0 < 2; ++i0)
            #pragma unroll
            for (int i1 = 0; i1 < 2; ++i1) {
                p01[i0 * 2 + i1] = cmul(i0 ? gb[0] : ga[0], i1 ? gb[1] : ga[1]);
                p23[i0 * 2 + i1] = cmul(i0 ? gb[2] : ga[2], i1 ? gb[3] : ga[3]);
            }
        #pragma unroll
        for (int hi = 0; hi < 4; ++hi)
            #pragma unroll
            for (int lo = 0; lo < 4; ++lo)
                amp[hi * 4 + lo] = cmul(p01[hi], p23[lo]);
    }

    const int cn_c[8] = {0, 1, 2, 3, 0, 1, 2, 3};
    const int cn_t[8] = {1, 2, 3, 0, 2, 3, 0, 1};
    for (int l = 0; l < L; ++l) {
        #pragma unroll
        for (int p = 0; p < 8; ++p) {
            const int cm = 8 >> cn_c[p];
            const int tm = 8 >> cn_t[p];
            #pragma unroll
            for (int i = 0; i < 16; ++i)
                if ((i & cm) && !(i & tm)) {
                    float2 tmp = amp[i]; amp[i] = amp[i | tm]; amp[i | tm] = tmp;
                }
        }
        #pragma unroll
        for (int w = 0; w < NQ; ++w) {
            const int m = 8 >> w;
            float4 Ua = rots4[(l * NQ + w) * 2 + 0];
            float4 Ub = rots4[(l * NQ + w) * 2 + 1];
            float2 u00 = make_float2(Ua.x, Ua.y);
            float2 u01 = make_float2(Ua.z, Ua.w);
            float2 u10 = make_float2(Ub.x, Ub.y);
            float2 u11 = make_float2(Ub.z, Ub.w);
            #pragma unroll
            for (int i = 0; i < 16; ++i)
                if (!(i & m)) {
                    float2 a0 = amp[i], a1 = amp[i | m];
                    amp[i]     = cfma(u01, a1, cmul(u00, a0));
                    amp[i | m] = cfma(u11, a1, cmul(u10, a0));
                }
        }
    }

    float z0 = 0.f, z1 = 0.f, z2 = 0.f, z3 = 0.f;
    #pragma unroll
    for (int i = 0; i < 16; ++i) {
        float p = fmaf(amp[i].x, amp[i].x, amp[i].y * amp[i].y);
        z0 += (i & 8) ? -p : p;
        z1 += (i & 4) ? -p : p;
        z2 += (i & 2) ? -p : p;
        z3 += (i & 1) ? -p : p;
    }
    zs[wid * 32 + lane] = make_float4(z0, z1, z2, z3);
    __syncthreads();

    // ---- phase 3: out = z @ W2^T + b2, coalesced float4 stores ----
    #pragma unroll
    for (int k = 0; k < (ROWS * DOUT / 4) / THREADS; ++k) {   // 16 iters
        int q  = tid + k * THREADS;
        int r  = q >> 4;
        int j4 = q & 15;
        long row = rowBase + r;
        if (row < B) {
            float4 z = zs[r];
            const float4 w0  = *reinterpret_cast<const float4*>(&w2t[0][j4 * 4]);
            const float4 w1v = *reinterpret_cast<const float4*>(&w2t[1][j4 * 4]);
            const float4 w2v = *reinterpret_cast<const float4*>(&w2t[2][j4 * 4]);
            const float4 w3v = *reinterpret_cast<const float4*>(&w2t[3][j4 * 4]);
            float4 o = b2s4[j4];
            o.x = fmaf(z.x, w0.x, fmaf(z.y, w1v.x, fmaf(z.z, w2v.x, fmaf(z.w, w3v.x, o.x))));
            o.y = fmaf(z.x, w0.y, fmaf(z.y, w1v.y, fmaf(z.z, w2v.y, fmaf(z.w, w3v.y, o.y))));
            o.z = fmaf(z.x, w0.z, fmaf(z.y, w1v.z, fmaf(z.z, w2v.z, fmaf(z.w, w3v.z, o.z))));
            o.w = fmaf(z.x, w0.w, fmaf(z.y, w1v.w, fmaf(z.z, w2v.w, fmaf(z.w, w3v.w, o.w))));
            reinterpret_cast<float4*>(out + row * DOUT)[j4] = o;
        }
    }
}

extern "C" void kernel_launch(void* const* d_in, const int* in_sizes, int n_in,
                              void* d_out, int out_size) {
    const float* x       = (const float*)d_in[0];
    const float* W1      = (const float*)d_in[1];
    const float* b1      = (const float*)d_in[2];
    const float* weights = (const float*)d_in[3];
    const float* W2      = (const float*)d_in[4];
    const float* b2      = (const float*)d_in[5];
    float* out = (float*)d_out;

    int B = in_sizes[0] / DIN;
    int L = in_sizes[3] / (NQ * 3);
    if (L > MAX_L) L = MAX_L;

    int grid = (B + ROWS - 1) / ROWS;
    qproj_fused<<<grid, THREADS>>>(x, W1, b1, weights, W2, b2, out, B, L);
}

// round 8
// speedup vs baseline: 1.1372x; 1.1372x over previous
#include <cuda_runtime.h>
#include <math.h>
#include <stdint.h>

// x:(B,256) f32, W1:(4,256), b1:(4), weights:(L,4,3), W2:(64,4), b2:(64) -> out:(B,64)
#define MAX_L   8
#define DIN     256
#define DOUT    64
#define NQ      4
#define ROWS    256
#define THREADS 256

__device__ __forceinline__ float2 cmul(float2 a, float2 b) {
    return make_float2(fmaf(a.x, b.x, -a.y * b.y), fmaf(a.x, b.y, a.y * b.x));
}
__device__ __forceinline__ float2 cfma(float2 u, float2 a, float2 acc) {
    acc.x = fmaf(u.x, a.x, fmaf(-u.y, a.y, acc.x));
    acc.y = fmaf(u.x, a.y, fmaf( u.y, a.x, acc.y));
    return acc;
}
// tanh via MUFU exp: tanh(x) = 1 - 2/(exp(2x)+1). |err| ~ 1e-7 rel.
__device__ __forceinline__ float fast_tanh(float v) {
    float e = __expf(2.f * v);
    return 1.f - 2.f * __frcp_rn(e + 1.f);
}

// ---- packed f32x2 helpers (Blackwell FFMA2; ptxas never auto-fuses) ----
__device__ __forceinline__ uint64_t pack2(float a, float b) {
    uint64_t d;
    asm("mov.b64 %0, {%1, %2};" : "=l"(d)
        : "r"(__float_as_uint(a)), "r"(__float_as_uint(b)));
    return d;
}
__device__ __forceinline__ uint64_t packdup(float a) {
    uint64_t d;
    uint32_t u = __float_as_uint(a);
    asm("mov.b64 %0, {%1, %1};" : "=l"(d) : "r"(u));
    return d;
}
__device__ __forceinline__ uint64_t mul2(uint64_t a, uint64_t b) {
    uint64_t d;
    asm("mul.rn.f32x2 %0, %1, %2;" : "=l"(d) : "l"(a), "l"(b));
    return d;
}
__device__ __forceinline__ uint64_t fma2(uint64_t a, uint64_t b, uint64_t c) {
    uint64_t d;
    asm("fma.rn.f32x2 %0, %1, %2, %3;" : "=l"(d) : "l"(a), "l"(b), "l"(c));
    return d;
}
__device__ __forceinline__ void unpack2(uint64_t v, float& lo, float& hi) {
    uint32_t l, h;
    asm("mov.b64 {%0, %1}, %2;" : "=r"(l), "=r"(h) : "l"(v));
    lo = __uint_as_float(l); hi = __uint_as_float(h);
}

// ---- circuit layers (templated so L=2 fully unrolls; CNOTs = renames) ----
template <int LL>
__device__ __forceinline__ void run_layers(float2 (&amp)[16], const float4* rots4) {
    const int cn_c[8] = {0, 1, 2, 3, 0, 1, 2, 3};
    const int cn_t[8] = {1, 2, 3, 0, 2, 3, 0, 1};
    #pragma unroll
    for (int l = 0; l < LL; ++l) {
        #pragma unroll
        for (int p = 0; p < 8; ++p) {
            const int cm = 8 >> cn_c[p];
            const int tm = 8 >> cn_t[p];
            #pragma unroll
            for (int i = 0; i < 16; ++i)
                if ((i & cm) && !(i & tm)) {
                    float2 tmp = amp[i]; amp[i] = amp[i | tm]; amp[i | tm] = tmp;
                }
        }
        #pragma unroll
        for (int w = 0; w < NQ; ++w) {
            const int m = 8 >> w;
            float4 Ua = rots4[(l * NQ + w) * 2 + 0];
            float4 Ub = rots4[(l * NQ + w) * 2 + 1];
            float2 u00 = make_float2(Ua.x, Ua.y);
            float2 u01 = make_float2(Ua.z, Ua.w);
            float2 u10 = make_float2(Ub.x, Ub.y);
            float2 u11 = make_float2(Ub.z, Ub.w);
            #pragma unroll
            for (int i = 0; i < 16; ++i)
                if (!(i & m)) {
                    float2 a0 = amp[i], a1 = amp[i | m];
                    amp[i]     = cfma(u01, a1, cmul(u00, a0));
                    amp[i | m] = cfma(u11, a1, cmul(u10, a0));
                }
        }
    }
}
__device__ void run_layers_dyn(float2 (&amp)[16], const float4* rots4, int L) {
    for (int l = 0; l < L; ++l) {
        const int cn_c[8] = {0, 1, 2, 3, 0, 1, 2, 3};
        const int cn_t[8] = {1, 2, 3, 0, 2, 3, 0, 1};
        #pragma unroll
        for (int p = 0; p < 8; ++p) {
            const int cm = 8 >> cn_c[p];
            const int tm = 8 >> cn_t[p];
            #pragma unroll
            for (int i = 0; i < 16; ++i)
                if ((i & cm) && !(i & tm)) {
                    float2 tmp = amp[i]; amp[i] = amp[i | tm]; amp[i | tm] = tmp;
                }
        }
        #pragma unroll
        for (int w = 0; w < NQ; ++w) {
            const int m = 8 >> w;
            float4 Ua = rots4[(l * NQ + w) * 2 + 0];
            float4 Ub = rots4[(l * NQ + w) * 2 + 1];
            float2 u00 = make_float2(Ua.x, Ua.y);
            float2 u01 = make_float2(Ua.z, Ua.w);
            float2 u10 = make_float2(Ub.x, Ub.y);
            float2 u11 = make_float2(Ub.z, Ub.w);
            #pragma unroll
            for (int i = 0; i < 16; ++i)
                if (!(i & m)) {
                    float2 a0 = amp[i], a1 = amp[i | m];
                    amp[i]     = cfma(u01, a1, cmul(u00, a0));
                    amp[i | m] = cfma(u11, a1, cmul(u10, a0));
                }
        }
    }
}

// ---------------------------------------------------------------------------
// Single fused kernel (R5 config: W1 in regs, 2 blocks/SM).
// Phase 1: warp-coop GEMV with FFMA2-packed weights; full value-halving
//   butterfly (16 SHFL) terminating in a 16-lane STS; f read back via LDS.128.
// Phase 2: per-lane 4-qubit circuit (L=2 specialized).
// Phase 3: z staged in smem, coalesced float4 projection stores.
// ---------------------------------------------------------------------------
__global__ void __launch_bounds__(THREADS, 2)
qproj_fused(const float* __restrict__ x,  const float* __restrict__ W1,
            const float* __restrict__ b1, const float* __restrict__ weights,
            const float* __restrict__ W2, const float* __restrict__ b2,
            float* __restrict__ out, int B, int L)
{
    __shared__ float  w2t[NQ][DOUT];
    __shared__ float4 b2s4[DOUT / 4];
    __shared__ float4 rots4[MAX_L * NQ * 2];
    __shared__ float4 fs4[ROWS];            // per-row f (4 floats)
    __shared__ float4 zs[ROWS];

    const int  tid     = threadIdx.x;
    const int  lane    = tid & 31;
    const int  wid     = tid >> 5;
    const long rowBase = (long)blockIdx.x * ROWS;
    const bool fullBlk = (rowBase + ROWS) <= (long)B;

    // ---- stage small weights + compute Rot matrices in-block ----
    if (tid < DOUT) {
        #pragma unroll
        for (int i = 0; i < NQ; ++i) w2t[i][tid] = W2[tid * NQ + i];
    }
    if (tid < DOUT / 4) b2s4[tid] = reinterpret_cast<const float4*>(b2)[tid];
    if (tid >= 64 && tid < 64 + L * NQ) {
        int idx = tid - 64;                 // l*4 + wire
        float phi = weights[idx * 3 + 0];
        float th  = weights[idx * 3 + 1];
        float om  = weights[idx * 3 + 2];
        float s, c;   sincosf(0.5f * th, &s, &c);
        float sa, ca; sincosf(0.5f * (phi - om), &sa, &ca);   // (phi-omega)/2
        float sb, cb; sincosf(0.5f * (phi + om), &sb, &cb);   // (phi+omega)/2
        rots4[idx * 2 + 0] = make_float4( cb * c, -sb * c,    // U00
                                         -ca * s, -sa * s);   // U01
        rots4[idx * 2 + 1] = make_float4( ca * s, -sa * s,    // U10
                                          cb * c,  sb * c);   // U11
    }

    // ---- phase 1: f = tanh(x @ W1^T + b1) * pi ----
    // Packed weights: wp01[e] = (W1[0][col_e], W1[1][col_e]); wp23 = q2,q3.
    // Lane covers cols 4*lane..+3 (A) and 128+4*lane..+3 (B). 16 uint64 total.
    uint64_t wA01[4], wA23[4], wB01[4], wB23[4];
    {
        float4 w0a = *reinterpret_cast<const float4*>(W1 + 0 * DIN + 4 * lane);
        float4 w1a = *reinterpret_cast<const float4*>(W1 + 1 * DIN + 4 * lane);
        float4 w2a = *reinterpret_cast<const float4*>(W1 + 2 * DIN + 4 * lane);
        float4 w3a = *reinterpret_cast<const float4*>(W1 + 3 * DIN + 4 * lane);
        wA01[0] = pack2(w0a.x, w1a.x); wA01[1] = pack2(w0a.y, w1a.y);
        wA01[2] = pack2(w0a.z, w1a.z); wA01[3] = pack2(w0a.w, w1a.w);
        wA23[0] = pack2(w2a.x, w3a.x); wA23[1] = pack2(w2a.y, w3a.y);
        wA23[2] = pack2(w2a.z, w3a.z); wA23[3] = pack2(w2a.w, w3a.w);
        float4 w0b = *reinterpret_cast<const float4*>(W1 + 0 * DIN + 128 + 4 * lane);
        float4 w1b = *reinterpret_cast<const float4*>(W1 + 1 * DIN + 128 + 4 * lane);
        float4 w2b = *reinterpret_cast<const float4*>(W1 + 2 * DIN + 128 + 4 * lane);
        float4 w3b = *reinterpret_cast<const float4*>(W1 + 3 * DIN + 128 + 4 * lane);
        wB01[0] = pack2(w0b.x, w1b.x); wB01[1] = pack2(w0b.y, w1b.y);
        wB01[2] = pack2(w0b.z, w1b.z); wB01[3] = pack2(w0b.w, w1b.w);
        wB23[0] = pack2(w2b.x, w3b.x); wB23[1] = pack2(w2b.y, w3b.y);
        wB23[2] = pack2(w2b.z, w3b.z); wB23[3] = pack2(w2b.w, w3b.w);
    }
    const float4 b1v = *reinterpret_cast<const float4*>(b1);

    const long warpRow = rowBase + wid * 32;
    const bool hiR1 = (lane & 16) != 0;
    const bool hiR0 = (lane & 8)  != 0;
    const bool hiQ1 = (lane & 4)  != 0;
    const bool hiQ0 = (lane & 2)  != 0;
    float* fsf = reinterpret_cast<float*>(fs4);

    #pragma unroll
    for (int s = 0; s < 8; ++s) {
        float4 xa[4], xb[4];
        if (fullBlk) {
            #pragma unroll
            for (int r = 0; r < 4; ++r) {            // 8 LDG.128 in flight
                const float* xp = x + (warpRow + s * 4 + r) * DIN + 4 * lane;
                xa[r] = *reinterpret_cast<const float4*>(xp);
                xb[r] = *reinterpret_cast<const float4*>(xp + 128);
            }
        } else {
            #pragma unroll
            for (int r = 0; r < 4; ++r) {
                long rr = warpRow + s * 4 + r;
                if (rr >= B) rr = (long)B - 1;
                const float* xp = x + rr * DIN + 4 * lane;
                xa[r] = *reinterpret_cast<const float4*>(xp);
                xb[r] = *reinterpret_cast<const float4*>(xp + 128);
            }
        }
        float acc[4][NQ];
        #pragma unroll
        for (int r = 0; r < 4; ++r) {
            uint64_t px;
            px = packdup(xa[r].x);
            uint64_t a01 = mul2(px, wA01[0]);
            uint64_t a23 = mul2(px, wA23[0]);
            px = packdup(xa[r].y);
            a01 = fma2(px, wA01[1], a01); a23 = fma2(px, wA23[1], a23);
            px = packdup(xa[r].z);
            a01 = fma2(px, wA01[2], a01); a23 = fma2(px, wA23[2], a23);
            px = packdup(xa[r].w);
            a01 = fma2(px, wA01[3], a01); a23 = fma2(px, wA23[3], a23);
            px = packdup(xb[r].x);
            a01 = fma2(px, wB01[0], a01); a23 = fma2(px, wB23[0], a23);
            px = packdup(xb[r].y);
            a01 = fma2(px, wB01[1], a01); a23 = fma2(px, wB23[1], a23);
            px = packdup(xb[r].z);
            a01 = fma2(px, wB01[2], a01); a23 = fma2(px, wB23[2], a23);
            px = packdup(xb[r].w);
            a01 = fma2(px, wB01[3], a01); a23 = fma2(px, wB23[3], a23);
            unpack2(a01, acc[r][0], acc[r][1]);
            unpack2(a23, acc[r][2], acc[r][3]);
        }

        // ---- full value-halving butterfly (16 SHFL total) ----
        float t8[2][NQ];
        #pragma unroll
        for (int rl = 0; rl < 2; ++rl)
            #pragma unroll
            for (int q = 0; q < NQ; ++q) {
                float kp = hiR1 ? acc[rl + 2][q] : acc[rl][q];
                float gv = hiR1 ? acc[rl][q]     : acc[rl + 2][q];
                t8[rl][q] = kp + __shfl_xor_sync(0xffffffffu, gv, 16);
            }
        float t4[NQ];
        #pragma unroll
        for (int q = 0; q < NQ; ++q) {
            float kp = hiR0 ? t8[1][q] : t8[0][q];
            float gv = hiR0 ? t8[0][q] : t8[1][q];
            t4[q] = kp + __shfl_xor_sync(0xffffffffu, gv, 8);
        }
        float t2[2];
        #pragma unroll
        for (int j = 0; j < 2; ++j) {
            float kp = hiQ1 ? t4[2 + j] : t4[j];
            float gv = hiQ1 ? t4[j]     : t4[2 + j];
            t2[j] = kp + __shfl_xor_sync(0xffffffffu, gv, 4);
        }
        float kp = hiQ0 ? t2[1] : t2[0];
        float gv = hiQ0 ? t2[0] : t2[1];
        float t1 = kp + __shfl_xor_sync(0xffffffffu, gv, 2);
        t1 += __shfl_xor_sync(0xffffffffu, t1, 1);
        // lane (even) holds row=(lane>>3), q=(lane>>1)&3 -> consecutive STS
        if (!(lane & 1))
            fsf[wid * 128 + s * 16 + (lane >> 1)] = t1;
    }
    __syncwarp();
    const float4 fraw = fs4[wid * 32 + lane];

    const float PI_F = 3.14159265358979323846f;
    float fv[NQ];
    fv[0] = fast_tanh(fraw.x + b1v.x) * PI_F;
    fv[1] = fast_tanh(fraw.y + b1v.y) * PI_F;
    fv[2] = fast_tanh(fraw.z + b1v.z) * PI_F;
    fv[3] = fast_tanh(fraw.w + b1v.w) * PI_F;

    // ---- phase 2: circuit (atan eliminated via identities) ----
    float2 ga[NQ], gb[NQ];
    #pragma unroll
    for (int i = 0; i < NQ; ++i) {
        float t  = fv[i];
        float t2v = t * t;
        float st = t * rsqrtf(1.f + t2v);
        float u  = sqrtf(fmaxf(0.5f * (1.f - st), 0.f));
        float v  = sqrtf(fmaxf(0.5f * (1.f + st), 0.f));
        float t4v = t2v * t2v;
        float r2 = rsqrtf(1.f + t4v);
        float cp = sqrtf(fmaxf(0.5f * (1.f + r2), 0.f));
        float sp = sqrtf(fmaxf(0.5f * (1.f - r2), 0.f));
        ga[i] = make_float2(u * cp, -u * sp);
        gb[i] = make_float2(v * cp,  v * sp);
    }

    float2 amp[16];
    {
        float2 p01[4], p23[4];
        #pragma unroll
        for (int i0 = 0; i0 < 2; ++i0)
            #pragma unroll
            for (int i1 = 0; i1 < 2; ++i1) {
                p01[i0 * 2 + i1] = cmul(i0 ? gb[0] : ga[0], i1 ? gb[1] : ga[1]);
                p23[i0 * 2 + i1] = cmul(i0 ? gb[2] : ga[2], i1 ? gb[3] : ga[3]);
            }
        #pragma unroll
        for (int hi = 0; hi < 4; ++hi)
            #pragma unroll
            for (int lo = 0; lo < 4; ++lo)
                amp[hi * 4 + lo] = cmul(p01[hi], p23[lo]);
    }

    __syncthreads();   // rots4/w2t/b2s4 staged

    if (L == 2)      run_layers<2>(amp, rots4);
    else             run_layers_dyn(amp, rots4, L);

    float z0 = 0.f, z1 = 0.f, z2 = 0.f, z3 = 0.f;
    #pragma unroll
    for (int i = 0; i < 16; ++i) {
        float p = fmaf(amp[i].x, amp[i].x, amp[i].y * amp[i].y);
        z0 += (i & 8) ? -p : p;
        z1 += (i & 4) ? -p : p;
        z2 += (i & 2) ? -p : p;
        z3 += (i & 1) ? -p : p;
    }
    zs[wid * 32 + lane] = make_float4(z0, z1, z2, z3);
    __syncthreads();

    // ---- phase 3: out = z @ W2^T + b2, coalesced float4 stores ----
    #pragma unroll
    for (int k = 0; k < (ROWS * DOUT / 4) / THREADS; ++k) {   // 16 iters
        int q  = tid + k * THREADS;
        int r  = q >> 4;
        int j4 = q & 15;
        long row = rowBase + r;
        if (row < B) {
            float4 z = zs[r];
            const float4 w0  = *reinterpret_cast<const float4*>(&w2t[0][j4 * 4]);
            const float4 w1v = *reinterpret_cast<const float4*>(&w2t[1][j4 * 4]);
            const float4 w2v = *reinterpret_cast<const float4*>(&w2t[2][j4 * 4]);
            const float4 w3v = *reinterpret_cast<const float4*>(&w2t[3][j4 * 4]);
            float4 o = b2s4[j4];
            o.x = fmaf(z.x, w0.x, fmaf(z.y, w1v.x, fmaf(z.z, w2v.x, fmaf(z.w, w3v.x, o.x))));
            o.y = fmaf(z.x, w0.y, fmaf(z.y, w1v.y, fmaf(z.z, w2v.y, fmaf(z.w, w3v.y, o.y))));
            o.z = fmaf(z.x, w0.z, fmaf(z.y, w1v.z, fmaf(z.z, w2v.z, fmaf(z.w, w3v.z, o.z))));
            o.w = fmaf(z.x, w0.w, fmaf(z.y, w1v.w, fmaf(z.z, w2v.w, fmaf(z.w, w3v.w, o.w))));
            reinterpret_cast<float4*>(out + row * DOUT)[j4] = o;
        }
    }
}

extern "C" void kernel_launch(void* const* d_in, const int* in_sizes, int n_in,
                              void* d_out, int out_size) {
    const float* x       = (const float*)d_in[0];
    const float* W1      = (const float*)d_in[1];
    const float* b1      = (const float*)d_in[2];
    const float* weights = (const float*)d_in[3];
    const float* W2      = (const float*)d_in[4];
    const float* b2      = (const float*)d_in[5];
    float* out = (float*)d_out;

    int B = in_sizes[0] / DIN;
    int L = in_sizes[3] / (NQ * 3);
    if (L > MAX_L) L = MAX_L;

    int grid = (B + ROWS - 1) / ROWS;
    qproj_fused<<<grid, THREADS>>>(x, W1, b1, weights, W2, b2, out, B, L);
}